// round 10
// baseline (speedup 1.0000x reference)
#include <cuda_runtime.h>
#include <cuda_bf16.h>
#include <math.h>

// Problem constants: B=2, L=4096, H=8, D=64, FACTOR=5 -> U_part = u = 45
#define L_SEQ 4096
#define NH 8
#define DDIM 64
#define NU 45
#define NS 45
#define NBH 16
#define CHUNK 128
#define NCHUNK 32              // 4096 / 128
#define PART_STRIDE 68         // [0]=m, [1]=l, [4..67]=acc (16B-aligned records)
#define NEG_BIG (-1e30f)
#define SKT_STRIDE 132         // K^T/P row stride (mult of 4 -> float4 rows)

// M-metric chunking
#define MCH 512                // keys per M-chunk
#define NMCH 8                 // 4096 / 512
#define MP_SMEM (MCH * DDIM * 4)   // 131072 B

// k_attn smem layout (dynamic): sQt 64x48 | sKT 64x132 | sV 128x64
#define SQT_FLOATS (64 * 48)
#define SKT_FLOATS (64 * SKT_STRIDE)
#define SV_FLOATS  (128 * 64)
#define SMEM_BYTES ((SQT_FLOATS + SKT_FLOATS + SV_FLOATS) * 4)   // 78,848 B

// ---------------- scratch (no allocations allowed) ----------------
__device__ int    g_sidx[L_SEQ * NS];          // samples bucketed by chunk
__device__ int    g_seg[L_SEQ * (NMCH + 1)];   // per-q chunk segment offsets
__device__ float2 g_Mp[NBH * NMCH * L_SEQ];    // per-chunk (max, sum) partials
__device__ float  g_M[NBH * L_SEQ];
__device__ int    g_topk[NBH * NU];
__device__ float  g_part[NBH * NCHUNK * NU * PART_STRIDE];

// ---------------- threefry2x32 (JAX partitionable) ----------------
#define TF_ROUND(x0, x1, r) do { (x0) += (x1); (x1) = ((x1) << (r)) | ((x1) >> (32 - (r))); (x1) ^= (x0); } while (0)

__host__ __device__ inline void tf2x32(unsigned k0, unsigned k1, unsigned &x0, unsigned &x1) {
    unsigned ks0 = k0, ks1 = k1, ks2 = k0 ^ k1 ^ 0x1BD11BDAu;
    x0 += ks0; x1 += ks1;
    TF_ROUND(x0, x1, 13); TF_ROUND(x0, x1, 15); TF_ROUND(x0, x1, 26); TF_ROUND(x0, x1, 6);
    x0 += ks1; x1 += ks2 + 1u;
    TF_ROUND(x0, x1, 17); TF_ROUND(x0, x1, 29); TF_ROUND(x0, x1, 16); TF_ROUND(x0, x1, 24);
    x0 += ks2; x1 += ks0 + 2u;
    TF_ROUND(x0, x1, 13); TF_ROUND(x0, x1, 15); TF_ROUND(x0, x1, 26); TF_ROUND(x0, x1, 6);
    x0 += ks0; x1 += ks1 + 3u;
    TF_ROUND(x0, x1, 17); TF_ROUND(x0, x1, 29); TF_ROUND(x0, x1, 16); TF_ROUND(x0, x1, 24);
    x0 += ks1; x1 += ks2 + 4u;
    TF_ROUND(x0, x1, 13); TF_ROUND(x0, x1, 15); TF_ROUND(x0, x1, 26); TF_ROUND(x0, x1, 6);
    x0 += ks2; x1 += ks0 + 5u;
}

// Thread per q: generate 45 sample indices (partitionable threefry:
// counter (0, q*45+s), out = lane0^lane1, & 0xFFF), bucket by 512-key chunk.
__global__ void k_idxsort(unsigned ka, unsigned kb) {
    int q = blockIdx.x * blockDim.x + threadIdx.x;
    if (q >= L_SEQ) return;
    int v[NS];
    int cnt[NMCH];
#pragma unroll
    for (int c = 0; c < NMCH; c++) cnt[c] = 0;
#pragma unroll
    for (int s = 0; s < NS; s++) {
        unsigned x0 = 0u, x1 = (unsigned)(q * NS + s);
        tf2x32(ka, kb, x0, x1);
        int k = (int)((x0 ^ x1) & 0xFFFu);
        v[s] = k;
        cnt[k >> 9]++;
    }
    int off[NMCH + 1];
    off[0] = 0;
#pragma unroll
    for (int c = 0; c < NMCH; c++) off[c + 1] = off[c] + cnt[c];
#pragma unroll
    for (int c = 0; c <= NMCH; c++) g_seg[q * (NMCH + 1) + c] = off[c];
    int pos[NMCH];
#pragma unroll
    for (int c = 0; c < NMCH; c++) pos[c] = off[c];
#pragma unroll
    for (int s = 0; s < NS; s++) {
        int c = v[s] >> 9;
        g_sidx[q * NS + pos[c]++] = v[s];
    }
}

// ---------------- M partials: block = (bh, 512-key chunk), K in smem ----------------
// Half-warp per query; 4-sample unroll interleaves shfl-reduce chains.
__global__ void __launch_bounds__(256) k_Mp(const float* __restrict__ Q, const float* __restrict__ K) {
    extern __shared__ float sK[];            // [512][64]
    int bh = blockIdx.x >> 3, c = blockIdx.x & 7;
    int b = bh >> 3, h = bh & 7;
    int t = threadIdx.x;
    int base = c * MCH;

    // stage K chunk (512 rows x 16 float4)
    for (int i = t; i < MCH * 16; i += 256) {
        int k = i >> 4, d4 = i & 15;
        ((float4*)sK)[i] = *(const float4*)(K + ((size_t)(b * L_SEQ + base + k) * NH + h) * DDIM + 4 * d4);
    }
    __syncthreads();

    int lane = t & 31, w = t >> 5, hw = lane >> 4, ld = lane & 15;
    unsigned hmask = 0xFFFFu << (16 * hw);
    int p = w * 2 + hw;                      // 0..15 half-warp slot

    for (int i = 0; i < L_SEQ / 16; i++) {
        int q = i * 16 + p;
        int s0 = g_seg[q * (NMCH + 1) + c];
        int s1 = g_seg[q * (NMCH + 1) + c + 1];
        float mx = NEG_BIG, sm = 0.0f;
        float4 qv = *(const float4*)(Q + ((size_t)(b * L_SEQ + q) * NH + h) * DDIM + 4 * ld);
        for (int j = s0; j < s1; j += 4) {
            float dot[4];
#pragma unroll
            for (int u = 0; u < 4; u++) {
                float d = NEG_BIG;
                if (j + u < s1) {
                    int k = g_sidx[q * NS + j + u] - base;
                    float4 kv = *(const float4*)&sK[(k << 6) + (ld << 2)];
                    d = qv.x * kv.x + qv.y * kv.y + qv.z * kv.z + qv.w * kv.w;
                }
                dot[u] = d;
            }
#pragma unroll
            for (int u = 0; u < 4; u++) {
                dot[u] += __shfl_xor_sync(hmask, dot[u], 8);
                dot[u] += __shfl_xor_sync(hmask, dot[u], 4);
                dot[u] += __shfl_xor_sync(hmask, dot[u], 2);
                dot[u] += __shfl_xor_sync(hmask, dot[u], 1);
            }
#pragma unroll
            for (int u = 0; u < 4; u++)
                if (j + u < s1) { mx = fmaxf(mx, dot[u]); sm += dot[u]; }
        }
        if (ld == 0) g_Mp[((bh * NMCH + c) << 12) + q] = make_float2(mx, sm);
    }
}

// combine chunk partials -> M
__global__ void k_Mc() {
    int i = blockIdx.x * blockDim.x + threadIdx.x;
    if (i >= NBH * L_SEQ) return;
    int bh = i >> 12, q = i & (L_SEQ - 1);
    float mx = NEG_BIG, sm = 0.0f;
#pragma unroll
    for (int c = 0; c < NMCH; c++) {
        float2 v = g_Mp[((bh * NMCH + c) << 12) + q];
        mx = fmaxf(mx, v.x);
        sm += v.y;
    }
    g_M[i] = mx - sm * (1.0f / (float)L_SEQ);
}

// ---------------- exact top-45 per (b,h): iterative argmax, 1024 threads ----------------
__global__ void __launch_bounds__(1024) k_topk() {
    __shared__ unsigned long long sk[L_SEQ];
    __shared__ unsigned long long red[32];
    int bh = blockIdx.x;
    int t = threadIdx.x, lane = t & 31, w = t >> 5;
    for (int i = t; i < L_SEQ; i += 1024) {
        unsigned u = __float_as_uint(g_M[bh * L_SEQ + i]);
        u = (u & 0x80000000u) ? ~u : (u | 0x80000000u);
        sk[i] = ((unsigned long long)u << 32) | (unsigned)(L_SEQ - 1 - i);
    }
    __syncthreads();
    for (int it = 0; it < NU; it++) {
        unsigned long long best = 0ull;
#pragma unroll
        for (int i = t; i < L_SEQ; i += 1024) best = max(best, sk[i]);
#pragma unroll
        for (int off = 16; off; off >>= 1) {
            unsigned long long o = __shfl_xor_sync(0xFFFFFFFFu, best, off);
            best = max(best, o);
        }
        if (lane == 0) red[w] = best;
        __syncthreads();
        if (t < 32) {
            unsigned long long b2 = red[t];
#pragma unroll
            for (int off = 16; off; off >>= 1) {
                unsigned long long o = __shfl_xor_sync(0xFFFFFFFFu, b2, off);
                b2 = max(b2, o);
            }
            if (t == 0) {
                int q = (L_SEQ - 1) - (int)(b2 & 0xFFFFFFFFu);
                g_topk[bh * NU + it] = q;
                sk[q] = 0ull;
            }
        }
        __syncthreads();
    }
}

// ---------------- attention partials (unchanged from R9) ----------------
__global__ void __launch_bounds__(256) k_attn(const float* __restrict__ Q, const float* __restrict__ K,
                       const float* __restrict__ V, const int* __restrict__ mask) {
    extern __shared__ float smem[];
    float* sQt = smem;                       // [d][u] stride 48
    float* sKT = smem + SQT_FLOATS;          // [d][k] stride 132; reused as P [u][k]
    float* sV  = smem + SQT_FLOATS + SKT_FLOATS; // [k][d] stride 64

    int bh = blockIdx.x >> 5, c = blockIdx.x & 31;
    int b = bh >> 3, h = bh & 7;
    int t = threadIdx.x;
    int tk = t & 31, tu = t >> 5;
    int k0 = c * CHUNK;

    for (int i = t; i < 64 * 48; i += 256) {
        int d = i / 48, u = i - d * 48;
        float v = 0.0f;
        if (u < NU) {
            int q = g_topk[bh * NU + u];
            v = Q[((size_t)(b * L_SEQ + q) * NH + h) * DDIM + d];
        }
        sQt[i] = v;
    }
    for (int i = t; i < CHUNK * 64; i += 256) {
        int k = i >> 6, d = i & 63;
        sKT[d * SKT_STRIDE + k] = K[((size_t)(b * L_SEQ + k0 + k) * NH + h) * DDIM + d];
    }
    for (int i = t; i < CHUNK * 64; i += 256) {
        int k = i >> 6, d = i & 63;
        sV[(k << 6) + d] = V[((size_t)(b * L_SEQ + k0 + k) * NH + h) * DDIM + d];
    }
    __syncthreads();

    float acc[6][4];
#pragma unroll
    for (int i = 0; i < 6; i++)
#pragma unroll
        for (int j = 0; j < 4; j++) acc[i][j] = 0.0f;

#pragma unroll 4
    for (int d = 0; d < 64; d++) {
        float2 q01 = *(float2*)&sQt[d * 48 + 6 * tu];
        float2 q23 = *(float2*)&sQt[d * 48 + 6 * tu + 2];
        float2 q45 = *(float2*)&sQt[d * 48 + 6 * tu + 4];
        float4 kv = *(float4*)&sKT[d * SKT_STRIDE + 4 * tk];
        acc[0][0] += q01.x * kv.x; acc[0][1] += q01.x * kv.y; acc[0][2] += q01.x * kv.z; acc[0][3] += q01.x * kv.w;
        acc[1][0] += q01.y * kv.x; acc[1][1] += q01.y * kv.y; acc[1][2] += q01.y * kv.z; acc[1][3] += q01.y * kv.w;
        acc[2][0] += q23.x * kv.x; acc[2][1] += q23.x * kv.y; acc[2][2] += q23.x * kv.z; acc[2][3] += q23.x * kv.w;
        acc[3][0] += q23.y * kv.x; acc[3][1] += q23.y * kv.y; acc[3][2] += q23.y * kv.z; acc[3][3] += q23.y * kv.w;
        acc[4][0] += q45.x * kv.x; acc[4][1] += q45.x * kv.y; acc[4][2] += q45.x * kv.z; acc[4][3] += q45.x * kv.w;
        acc[5][0] += q45.y * kv.x; acc[5][1] += q45.y * kv.y; acc[5][2] += q45.y * kv.z; acc[5][3] += q45.y * kv.w;
    }

    int4 mk = *(const int4*)&mask[b * L_SEQ + k0 + 4 * tk];
#pragma unroll
    for (int i = 0; i < 6; i++) {
        acc[i][0] = mk.x ? acc[i][0] * 0.125f : NEG_BIG;
        acc[i][1] = mk.y ? acc[i][1] * 0.125f : NEG_BIG;
        acc[i][2] = mk.z ? acc[i][2] * 0.125f : NEG_BIG;
        acc[i][3] = mk.w ? acc[i][3] * 0.125f : NEG_BIG;
    }

    float m_i[6], l_i[6];
#pragma unroll
    for (int i = 0; i < 6; i++) {
        float m = fmaxf(fmaxf(acc[i][0], acc[i][1]), fmaxf(acc[i][2], acc[i][3]));
#pragma unroll
        for (int off = 16; off; off >>= 1)
            m = fmaxf(m, __shfl_xor_sync(0xFFFFFFFFu, m, off));
        float l = 0.0f;
#pragma unroll
        for (int j = 0; j < 4; j++) {
            float e = (acc[i][j] <= 0.5f * NEG_BIG) ? 0.0f : __expf(acc[i][j] - m);
            acc[i][j] = e;
            l += e;
        }
#pragma unroll
        for (int off = 16; off; off >>= 1)
            l += __shfl_xor_sync(0xFFFFFFFFu, l, off);
        m_i[i] = m; l_i[i] = l;
    }
    __syncthreads();

#pragma unroll
    for (int i = 0; i < 6; i++) {
        int u = 6 * tu + i;
        *(float4*)&sKT[u * SKT_STRIDE + 4 * tk] = make_float4(acc[i][0], acc[i][1], acc[i][2], acc[i][3]);
        if (tk == 0 && u < NU) {
            float* part = g_part + ((size_t)blockIdx.x * NU + u) * PART_STRIDE;
            part[0] = m_i[i];
            part[1] = l_i[i];
        }
    }
    __syncthreads();

    int td = tk;
    float2 ob[6];
#pragma unroll
    for (int i = 0; i < 6; i++) ob[i] = make_float2(0.0f, 0.0f);

#pragma unroll 4
    for (int kk = 0; kk < CHUNK; kk++) {
        float2 vv = *(float2*)&sV[(kk << 6) + 2 * td];
        float p0 = sKT[(6 * tu + 0) * SKT_STRIDE + kk];
        float p1 = sKT[(6 * tu + 1) * SKT_STRIDE + kk];
        float p2 = sKT[(6 * tu + 2) * SKT_STRIDE + kk];
        float p3 = sKT[(6 * tu + 3) * SKT_STRIDE + kk];
        float p4 = sKT[(6 * tu + 4) * SKT_STRIDE + kk];
        float p5 = sKT[(6 * tu + 5) * SKT_STRIDE + kk];
        ob[0].x += p0 * vv.x; ob[0].y += p0 * vv.y;
        ob[1].x += p1 * vv.x; ob[1].y += p1 * vv.y;
        ob[2].x += p2 * vv.x; ob[2].y += p2 * vv.y;
        ob[3].x += p3 * vv.x; ob[3].y += p3 * vv.y;
        ob[4].x += p4 * vv.x; ob[4].y += p4 * vv.y;
        ob[5].x += p5 * vv.x; ob[5].y += p5 * vv.y;
    }
#pragma unroll
    for (int i = 0; i < 6; i++) {
        int u = 6 * tu + i;
        if (u < NU) {
            float* part = g_part + ((size_t)blockIdx.x * NU + u) * PART_STRIDE;
            *(float2*)&part[4 + 2 * td] = ob[i];
        }
    }
}

// ---------------- combine split-K partials ----------------
__global__ void k_comb(float* __restrict__ out) {
    int bu = blockIdx.x;
    int bh = bu / NU, u = bu % NU;
    int b = bh >> 3, h = bh & 7;
    int d = threadIdx.x;

    float m = NEG_BIG;
#pragma unroll 8
    for (int c = 0; c < NCHUNK; c++)
        m = fmaxf(m, g_part[((size_t)(bh * NCHUNK + c) * NU + u) * PART_STRIDE]);
    float l = 0.0f, acc = 0.0f;
#pragma unroll 8
    for (int c = 0; c < NCHUNK; c++) {
        const float* part = g_part + ((size_t)(bh * NCHUNK + c) * NU + u) * PART_STRIDE;
        float mc = part[0];
        float sc = (mc <= 0.5f * NEG_BIG) ? 0.0f : __expf(mc - m);
        l += part[1] * sc;
        acc += sc * part[4 + d];
    }
    out[((size_t)(b * NU + u) * NH + h) * DDIM + d] = acc / l;
}

// ---------------- launch ----------------
extern "C" void kernel_launch(void* const* d_in, const int* in_sizes, int n_in,
                              void* d_out, int out_size) {
    const float* Q = (const float*)d_in[0];
    const float* K = (const float*)d_in[1];
    const float* V = (const float*)d_in[2];
    const int* mask = (const int*)d_in[3];
    float* out = (float*)d_out;

    cudaFuncSetAttribute(k_attn, cudaFuncAttributeMaxDynamicSharedMemorySize, SMEM_BYTES);
    cudaFuncSetAttribute(k_Mp, cudaFuncAttributeMaxDynamicSharedMemorySize, MP_SMEM);

    // lower_key = 2nd child of foldlike split(key(1)) = tf2x32(key=(0,1), ctr=(0,1))
    unsigned s0 = 0u, s1 = 1u;
    tf2x32(0u, 1u, s0, s1);

    k_idxsort<<<L_SEQ / 256, 256>>>(s0, s1);
    k_Mp<<<NBH * NMCH, 256, MP_SMEM>>>(Q, K);
    k_Mc<<<(NBH * L_SEQ) / 256, 256>>>();
    k_topk<<<NBH, 1024>>>();
    k_attn<<<NBH * NCHUNK, 256, SMEM_BYTES>>>(Q, K, V, mask);
    k_comb<<<NBH * NU, 64>>>(out);
}

// round 11
// speedup vs baseline: 4.1879x; 4.1879x over previous
#include <cuda_runtime.h>
#include <cuda_bf16.h>
#include <math.h>

// Problem constants: B=2, L=4096, H=8, D=64, FACTOR=5 -> U_part = u = 45
#define L_SEQ 4096
#define NH 8
#define DDIM 64
#define NU 45
#define NS 45
#define NBH 16
#define NIDX (L_SEQ * NS)      // 184320
#define CHUNK 128
#define NCHUNK 32              // 4096 / 128
#define PART_STRIDE 68         // [0]=m, [1]=l, [4..67]=acc (16B-aligned records)
#define NEG_BIG (-1e30f)
#define SKT_STRIDE 132         // K^T/P row stride (mult of 4 -> float4 rows)

// k_attn smem (dynamic): sQt 64x48 | sKT 64x132 | sV 128x64
#define SQT_FLOATS (64 * 48)
#define SKT_FLOATS (64 * SKT_STRIDE)
#define SV_FLOATS  (128 * 64)
#define SMEM_BYTES ((SQT_FLOATS + SKT_FLOATS + SV_FLOATS) * 4)   // 78,848 B

// ---------------- scratch (no allocations allowed) ----------------
__device__ int   g_idx[NIDX];
__device__ float g_M[NBH * L_SEQ];
__device__ int   g_topk[NBH * NU];
__device__ float g_part[NBH * NCHUNK * NU * PART_STRIDE]; // 6.3 MB

// ---------------- threefry2x32 (JAX partitionable) ----------------
#define TF_ROUND(x0, x1, r) do { (x0) += (x1); (x1) = ((x1) << (r)) | ((x1) >> (32 - (r))); (x1) ^= (x0); } while (0)

__host__ __device__ inline void tf2x32(unsigned k0, unsigned k1, unsigned &x0, unsigned &x1) {
    unsigned ks0 = k0, ks1 = k1, ks2 = k0 ^ k1 ^ 0x1BD11BDAu;
    x0 += ks0; x1 += ks1;
    TF_ROUND(x0, x1, 13); TF_ROUND(x0, x1, 15); TF_ROUND(x0, x1, 26); TF_ROUND(x0, x1, 6);
    x0 += ks1; x1 += ks2 + 1u;
    TF_ROUND(x0, x1, 17); TF_ROUND(x0, x1, 29); TF_ROUND(x0, x1, 16); TF_ROUND(x0, x1, 24);
    x0 += ks2; x1 += ks0 + 2u;
    TF_ROUND(x0, x1, 13); TF_ROUND(x0, x1, 15); TF_ROUND(x0, x1, 26); TF_ROUND(x0, x1, 6);
    x0 += ks0; x1 += ks1 + 3u;
    TF_ROUND(x0, x1, 17); TF_ROUND(x0, x1, 29); TF_ROUND(x0, x1, 16); TF_ROUND(x0, x1, 24);
    x0 += ks1; x1 += ks2 + 4u;
    TF_ROUND(x0, x1, 13); TF_ROUND(x0, x1, 15); TF_ROUND(x0, x1, 26); TF_ROUND(x0, x1, 6);
    x0 += ks2; x1 += ks0 + 5u;
}

// random_bits: element i uses counter (0, i); output = out0 ^ out1; & 0xFFF.
__global__ void k_idx(unsigned k2a, unsigned k2b) {
    int i = blockIdx.x * blockDim.x + threadIdx.x;
    if (i >= NIDX) return;
    unsigned x0 = 0u, x1 = (unsigned)i;
    tf2x32(k2a, k2b, x0, x1);
    g_idx[i] = (int)((x0 ^ x1) & 0xFFFu);
}

// ---------------- M metric: warp per (b,h,q), half-warp per sample ----------------
__global__ void k_M(const float* __restrict__ Q, const float* __restrict__ K) {
    int warp = (blockIdx.x * blockDim.x + threadIdx.x) >> 5;
    int lane = threadIdx.x & 31;
    if (warp >= NBH * L_SEQ) return;
    int q = warp & (L_SEQ - 1);
    int bh = warp >> 12;
    int b = bh >> 3, h = bh & 7;
    int hw = lane >> 4, ld = lane & 15;

    float4 qv = *(const float4*)(Q + ((size_t)(b * L_SEQ + q) * NH + h) * DDIM + 4 * ld);
    const float* Kb = K + (size_t)b * (L_SEQ * NH * DDIM) + (size_t)h * DDIM;
    const int* idxp = g_idx + q * NS;

    float mx = NEG_BIG, sm = 0.0f;
#pragma unroll
    for (int s = 0; s < NS; s += 2) {
        int s0 = s + hw;
        int i = (s0 < NS) ? s0 : (NS - 1);
        int k = idxp[i];
        float4 kv = *(const float4*)(Kb + (size_t)k * (NH * DDIM) + 4 * ld);
        float p = qv.x * kv.x + qv.y * kv.y + qv.z * kv.z + qv.w * kv.w;
        p += __shfl_xor_sync(0xFFFFFFFFu, p, 8);
        p += __shfl_xor_sync(0xFFFFFFFFu, p, 4);
        p += __shfl_xor_sync(0xFFFFFFFFu, p, 2);
        p += __shfl_xor_sync(0xFFFFFFFFu, p, 1);
        if (s0 < NS) { mx = fmaxf(mx, p); sm += p; }
    }
    mx = fmaxf(mx, __shfl_xor_sync(0xFFFFFFFFu, mx, 16));
    sm += __shfl_xor_sync(0xFFFFFFFFu, sm, 16);
    if (lane == 0) g_M[warp] = mx - sm * (1.0f / (float)L_SEQ);
}

// ---------------- exact top-45: hierarchical max-tree, warp-0 selection loop ----------------
// Keys: ordered-float in high 32, (4095-q) in low 32 -> max = (largest value, smallest q).
// Build 128 group-maxes (32 elems/group); per iteration, warp 0 argmaxes 128 gmax,
// rescans only the winner's group, updates its gmax. No block barriers in the loop.
__global__ void __launch_bounds__(1024) k_topk() {
    __shared__ unsigned long long sk[L_SEQ];
    __shared__ unsigned long long gmax[128];
    int bh = blockIdx.x;
    int t = threadIdx.x, lane = t & 31, w = t >> 5;

    for (int i = t; i < L_SEQ; i += 1024) {
        unsigned u = __float_as_uint(g_M[bh * L_SEQ + i]);
        u = (u & 0x80000000u) ? ~u : (u | 0x80000000u);
        sk[i] = ((unsigned long long)u << 32) | (unsigned)(L_SEQ - 1 - i);
    }
    __syncthreads();

    // build group maxes: warp w -> groups w, w+32, w+64, w+96
#pragma unroll
    for (int g = w; g < 128; g += 32) {
        unsigned long long v = sk[g * 32 + lane];
#pragma unroll
        for (int off = 16; off; off >>= 1) {
            unsigned long long o = __shfl_xor_sync(0xFFFFFFFFu, v, off);
            v = (o > v) ? o : v;
        }
        if (lane == 0) gmax[g] = v;
    }
    __syncthreads();

    if (w == 0) {
        for (int it = 0; it < NU; it++) {
            unsigned long long a = gmax[lane], b2 = gmax[lane + 32];
            unsigned long long c = gmax[lane + 64], d = gmax[lane + 96];
            unsigned long long v = a > b2 ? a : b2;
            unsigned long long v2 = c > d ? c : d;
            v = v > v2 ? v : v2;
#pragma unroll
            for (int off = 16; off; off >>= 1) {
                unsigned long long o = __shfl_xor_sync(0xFFFFFFFFu, v, off);
                v = (o > v) ? o : v;
            }
            int q = (L_SEQ - 1) - (int)(v & 0xFFFFFFFFu);
            if (lane == 0) {
                g_topk[bh * NU + it] = q;
                sk[q] = 0ull;
            }
            __syncwarp();
            int g = q >> 5;
            unsigned long long x = sk[g * 32 + lane];
#pragma unroll
            for (int off = 16; off; off >>= 1) {
                unsigned long long o = __shfl_xor_sync(0xFFFFFFFFu, x, off);
                x = (o > x) ? o : x;
            }
            if (lane == 0) gmax[g] = x;
            __syncwarp();
        }
    }
}

// ---------------- attention partials (proven R9 version) ----------------
__global__ void __launch_bounds__(256) k_attn(const float* __restrict__ Q, const float* __restrict__ K,
                       const float* __restrict__ V, const int* __restrict__ mask) {
    extern __shared__ float smem[];
    float* sQt = smem;                       // [d][u] stride 48
    float* sKT = smem + SQT_FLOATS;          // [d][k] stride 132; reused as P [u][k]
    float* sV  = smem + SQT_FLOATS + SKT_FLOATS; // [k][d] stride 64

    int bh = blockIdx.x >> 5, c = blockIdx.x & 31;
    int b = bh >> 3, h = bh & 7;
    int t = threadIdx.x;
    int tk = t & 31, tu = t >> 5;
    int k0 = c * CHUNK;

    for (int i = t; i < 64 * 48; i += 256) {
        int d = i / 48, u = i - d * 48;
        float v = 0.0f;
        if (u < NU) {
            int q = g_topk[bh * NU + u];
            v = Q[((size_t)(b * L_SEQ + q) * NH + h) * DDIM + d];
        }
        sQt[i] = v;
    }
    for (int i = t; i < CHUNK * 64; i += 256) {
        int k = i >> 6, d = i & 63;
        sKT[d * SKT_STRIDE + k] = K[((size_t)(b * L_SEQ + k0 + k) * NH + h) * DDIM + d];
    }
    for (int i = t; i < CHUNK * 64; i += 256) {
        int k = i >> 6, d = i & 63;
        sV[(k << 6) + d] = V[((size_t)(b * L_SEQ + k0 + k) * NH + h) * DDIM + d];
    }
    __syncthreads();

    float acc[6][4];
#pragma unroll
    for (int i = 0; i < 6; i++)
#pragma unroll
        for (int j = 0; j < 4; j++) acc[i][j] = 0.0f;

#pragma unroll 4
    for (int d = 0; d < 64; d++) {
        float2 q01 = *(float2*)&sQt[d * 48 + 6 * tu];
        float2 q23 = *(float2*)&sQt[d * 48 + 6 * tu + 2];
        float2 q45 = *(float2*)&sQt[d * 48 + 6 * tu + 4];
        float4 kv = *(float4*)&sKT[d * SKT_STRIDE + 4 * tk];
        acc[0][0] += q01.x * kv.x; acc[0][1] += q01.x * kv.y; acc[0][2] += q01.x * kv.z; acc[0][3] += q01.x * kv.w;
        acc[1][0] += q01.y * kv.x; acc[1][1] += q01.y * kv.y; acc[1][2] += q01.y * kv.z; acc[1][3] += q01.y * kv.w;
        acc[2][0] += q23.x * kv.x; acc[2][1] += q23.x * kv.y; acc[2][2] += q23.x * kv.z; acc[2][3] += q23.x * kv.w;
        acc[3][0] += q23.y * kv.x; acc[3][1] += q23.y * kv.y; acc[3][2] += q23.y * kv.z; acc[3][3] += q23.y * kv.w;
        acc[4][0] += q45.x * kv.x; acc[4][1] += q45.x * kv.y; acc[4][2] += q45.x * kv.z; acc[4][3] += q45.x * kv.w;
        acc[5][0] += q45.y * kv.x; acc[5][1] += q45.y * kv.y; acc[5][2] += q45.y * kv.z; acc[5][3] += q45.y * kv.w;
    }

    int4 mk = *(const int4*)&mask[b * L_SEQ + k0 + 4 * tk];
#pragma unroll
    for (int i = 0; i < 6; i++) {
        acc[i][0] = mk.x ? acc[i][0] * 0.125f : NEG_BIG;
        acc[i][1] = mk.y ? acc[i][1] * 0.125f : NEG_BIG;
        acc[i][2] = mk.z ? acc[i][2] * 0.125f : NEG_BIG;
        acc[i][3] = mk.w ? acc[i][3] * 0.125f : NEG_BIG;
    }

    float m_i[6], l_i[6];
#pragma unroll
    for (int i = 0; i < 6; i++) {
        float m = fmaxf(fmaxf(acc[i][0], acc[i][1]), fmaxf(acc[i][2], acc[i][3]));
#pragma unroll
        for (int off = 16; off; off >>= 1)
            m = fmaxf(m, __shfl_xor_sync(0xFFFFFFFFu, m, off));
        float l = 0.0f;
#pragma unroll
        for (int j = 0; j < 4; j++) {
            float e = (acc[i][j] <= 0.5f * NEG_BIG) ? 0.0f : __expf(acc[i][j] - m);
            acc[i][j] = e;
            l += e;
        }
#pragma unroll
        for (int off = 16; off; off >>= 1)
            l += __shfl_xor_sync(0xFFFFFFFFu, l, off);
        m_i[i] = m; l_i[i] = l;
    }
    __syncthreads();

#pragma unroll
    for (int i = 0; i < 6; i++) {
        int u = 6 * tu + i;
        *(float4*)&sKT[u * SKT_STRIDE + 4 * tk] = make_float4(acc[i][0], acc[i][1], acc[i][2], acc[i][3]);
        if (tk == 0 && u < NU) {
            float* part = g_part + ((size_t)blockIdx.x * NU + u) * PART_STRIDE;
            part[0] = m_i[i];
            part[1] = l_i[i];
        }
    }
    __syncthreads();

    int td = tk;
    float2 ob[6];
#pragma unroll
    for (int i = 0; i < 6; i++) ob[i] = make_float2(0.0f, 0.0f);

#pragma unroll 4
    for (int kk = 0; kk < CHUNK; kk++) {
        float2 vv = *(float2*)&sV[(kk << 6) + 2 * td];
        float p0 = sKT[(6 * tu + 0) * SKT_STRIDE + kk];
        float p1 = sKT[(6 * tu + 1) * SKT_STRIDE + kk];
        float p2 = sKT[(6 * tu + 2) * SKT_STRIDE + kk];
        float p3 = sKT[(6 * tu + 3) * SKT_STRIDE + kk];
        float p4 = sKT[(6 * tu + 4) * SKT_STRIDE + kk];
        float p5 = sKT[(6 * tu + 5) * SKT_STRIDE + kk];
        ob[0].x += p0 * vv.x; ob[0].y += p0 * vv.y;
        ob[1].x += p1 * vv.x; ob[1].y += p1 * vv.y;
        ob[2].x += p2 * vv.x; ob[2].y += p2 * vv.y;
        ob[3].x += p3 * vv.x; ob[3].y += p3 * vv.y;
        ob[4].x += p4 * vv.x; ob[4].y += p4 * vv.y;
        ob[5].x += p5 * vv.x; ob[5].y += p5 * vv.y;
    }
#pragma unroll
    for (int i = 0; i < 6; i++) {
        int u = 6 * tu + i;
        if (u < NU) {
            float* part = g_part + ((size_t)blockIdx.x * NU + u) * PART_STRIDE;
            *(float2*)&part[4 + 2 * td] = ob[i];
        }
    }
}

// ---------------- combine split-K partials ----------------
__global__ void k_comb(float* __restrict__ out) {
    int bu = blockIdx.x;
    int bh = bu / NU, u = bu % NU;
    int b = bh >> 3, h = bh & 7;
    int d = threadIdx.x;

    float m = NEG_BIG;
#pragma unroll 8
    for (int c = 0; c < NCHUNK; c++)
        m = fmaxf(m, g_part[((size_t)(bh * NCHUNK + c) * NU + u) * PART_STRIDE]);
    float l = 0.0f, acc = 0.0f;
#pragma unroll 8
    for (int c = 0; c < NCHUNK; c++) {
        const float* part = g_part + ((size_t)(bh * NCHUNK + c) * NU + u) * PART_STRIDE;
        float mc = part[0];
        float sc = (mc <= 0.5f * NEG_BIG) ? 0.0f : __expf(mc - m);
        l += part[1] * sc;
        acc += sc * part[4 + d];
    }
    out[((size_t)(b * NU + u) * NH + h) * DDIM + d] = acc / l;
}

// ---------------- launch ----------------
extern "C" void kernel_launch(void* const* d_in, const int* in_sizes, int n_in,
                              void* d_out, int out_size) {
    const float* Q = (const float*)d_in[0];
    const float* K = (const float*)d_in[1];
    const float* V = (const float*)d_in[2];
    const int* mask = (const int*)d_in[3];
    float* out = (float*)d_out;

    cudaFuncSetAttribute(k_attn, cudaFuncAttributeMaxDynamicSharedMemorySize, SMEM_BYTES);

    // lower_key = 2nd child of foldlike split(key(1)) = tf2x32(key=(0,1), ctr=(0,1))
    unsigned s0 = 0u, s1 = 1u;
    tf2x32(0u, 1u, s0, s1);

    k_idx<<<(NIDX + 255) / 256, 256>>>(s0, s1);
    k_M<<<(NBH * L_SEQ) / 8, 256>>>(Q, K);
    k_topk<<<NBH, 1024>>>();
    k_attn<<<NBH * NCHUNK, 256, SMEM_BYTES>>>(Q, K, V, mask);
    k_comb<<<NBH * NU, 64>>>(out);
}